// round 3
// baseline (speedup 1.0000x reference)
#include <cuda_runtime.h>
#include <cstdint>

// CRF loss: mean_b( logZ_b - gold_b )
//   forward recurrence done in LINEAR space with power-of-two renormalization:
//     e_t[n] = (expM @ e_{t-1})[n] * 2^{-k_t} * exp(emit_t[n]),  off += k_t
//     alpha_t[n] = log(e_t[n]) + off * ln2
//   expM = exp(transitions) precomputed per-lane (lane = next-state row).
//   Gold score (emission gather + transition chain) folded into the same loop.

#define KSTATES   32
#define START_IDX 30
#define STOP_IDX  31
#define FULLMASK  0xffffffffu

__device__ float g_scratch[4096];

__global__ void __launch_bounds__(128)
crf_forward_kernel(const float* __restrict__ feats,
                   const float* __restrict__ trans,
                   const int*   __restrict__ tags,
                   const int*   __restrict__ lens,
                   int B, int T)
{
    const int warp_global = (blockIdx.x * blockDim.x + threadIdx.x) >> 5;
    const int lane = threadIdx.x & 31;
    if (warp_global >= B) return;
    const int b = warp_global;

    const float* fb = feats + (size_t)b * T * KSTATES + lane;
    const int*   tb = tags  + (size_t)b * T;
    const int    len = lens[b];

    // Per-lane row of exp(transitions): lane n holds expM[n][p], p=0..31.
    // exp(-10000) flushes to exactly 0 -> constraint rows/cols are free.
    float M[KSTATES];
#pragma unroll
    for (int p = 0; p < KSTATES; p++)
        M[p] = __expf(trans[lane * KSTATES + p]);

    // State: e[lane], with integer log2-offset 'off' (lane-uniform).
    float e = (lane == START_IDX) ? 1.0f : 0.0f;
    int   off = 0;

    float g_emit = 0.0f;   // gold emission score (per-lane partial)
    float g_tr   = 0.0f;   // gold transition score (lane-uniform, broadcast loads)
    int   tprev  = START_IDX;

    // 4-deep prefetch pipeline for emissions + tags.
    float fbuf[4]; int tbuf[4];
#pragma unroll
    for (int i = 0; i < 4; i++) {
        bool v  = (i < len);
        fbuf[i] = v ? fb[(size_t)i * KSTATES] : 0.0f;
        tbuf[i] = v ? tb[i] : 0;
    }

    for (int t0 = 0; t0 < len; t0 += 4) {
        // Prefetch the next unrolled block (covers DRAM latency ~577cyc).
        float fn[4]; int tn[4];
#pragma unroll
        for (int i = 0; i < 4; i++) {
            int tt = t0 + 4 + i;
            bool v = (tt < len);
            fn[i] = v ? fb[(size_t)tt * KSTATES] : 0.0f;
            tn[i] = v ? tb[tt] : 0;
        }

#pragma unroll
        for (int i = 0; i < 4; i++) {
            if (t0 + i < len) {   // uniform across warp
                float expE = __expf(fbuf[i]);     // off critical path (prefetched input)

                // s[n] = sum_p expM[n][p] * e[p]  via warp broadcast
                float s0 = 0.f, s1 = 0.f, s2 = 0.f, s3 = 0.f;
#pragma unroll
                for (int p = 0; p < KSTATES; p += 4) {
                    s0 = fmaf(M[p    ], __shfl_sync(FULLMASK, e, p    ), s0);
                    s1 = fmaf(M[p + 1], __shfl_sync(FULLMASK, e, p + 1), s1);
                    s2 = fmaf(M[p + 2], __shfl_sync(FULLMASK, e, p + 2), s2);
                    s3 = fmaf(M[p + 3], __shfl_sync(FULLMASK, e, p + 3), s3);
                }
                float s = (s0 + s1) + (s2 + s3);

                // Power-of-two renorm from lane 0's value: exact integer log2 bookkeeping.
                float c = __shfl_sync(FULLMASK, s, 0);
                int ie  = (int)((__float_as_uint(c) >> 23) & 0xFF);
                float r = __uint_as_float((unsigned)(254 - ie) << 23); // 2^-(ie-127)
                off += ie - 127;

                e = s * r * expE;

                // Gold score accumulation (off critical path).
                int tg = tbuf[i];
                g_emit += (lane == tg) ? fbuf[i] : 0.0f;
                g_tr   += trans[tg * KSTATES + tprev];   // broadcast, L1-hot 4KB table
                tprev = tg;
            }
            fbuf[i] = fn[i];
            tbuf[i] = tn[i];
        }
    }

    // Gold: final transition to STOP.
    g_tr += trans[STOP_IDX * KSTATES + tprev];

    // forward_score = off*ln2 + log( sum_p exp(trans[STOP,p]) * e[p] )
    // = one more dot; take lane STOP's result (its M row IS exp(trans[STOP,:])).
    float s0 = 0.f, s1 = 0.f, s2 = 0.f, s3 = 0.f;
#pragma unroll
    for (int p = 0; p < KSTATES; p += 4) {
        s0 = fmaf(M[p    ], __shfl_sync(FULLMASK, e, p    ), s0);
        s1 = fmaf(M[p + 1], __shfl_sync(FULLMASK, e, p + 1), s1);
        s2 = fmaf(M[p + 2], __shfl_sync(FULLMASK, e, p + 2), s2);
        s3 = fmaf(M[p + 3], __shfl_sync(FULLMASK, e, p + 3), s3);
    }
    float sfin  = (s0 + s1) + (s2 + s3);
    float sstop = __shfl_sync(FULLMASK, sfin, STOP_IDX);
    float fwd   = (float)off * 0.693147180559945f + __logf(sstop);

    // Reduce gold emission partials across lanes.
#pragma unroll
    for (int d = 16; d; d >>= 1)
        g_emit += __shfl_xor_sync(FULLMASK, g_emit, d);

    if (lane == 0)
        g_scratch[b] = fwd - g_tr - g_emit;
}

__global__ void crf_reduce_kernel(float* __restrict__ out, int B)
{
    __shared__ float sh[512];
    int tid = threadIdx.x;
    float v = 0.0f;
    for (int i = tid; i < B; i += 512)
        v += g_scratch[i];
    sh[tid] = v;
    __syncthreads();
#pragma unroll
    for (int sft = 256; sft > 0; sft >>= 1) {
        if (tid < sft) sh[tid] += sh[tid + sft];
        __syncthreads();
    }
    if (tid == 0) out[0] = sh[0] / (float)B;
}

extern "C" void kernel_launch(void* const* d_in, const int* in_sizes, int n_in,
                              void* d_out, int out_size)
{
    const float* feats = (const float*)d_in[0];   // [B,T,K] f32
    const float* trans = (const float*)d_in[1];   // [K,K]   f32
    const int*   tags  = (const int*)  d_in[2];   // [B,T]   i32
    const int*   lens  = (const int*)  d_in[3];   // [B]     i32

    int B = in_sizes[3];
    int T = in_sizes[2] / B;

    const int warps_per_block = 4;                 // 1 block/SM, 1 warp/SMSP
    int blocks = (B + warps_per_block - 1) / warps_per_block;

    crf_forward_kernel<<<blocks, warps_per_block * 32>>>(feats, trans, tags, lens, B, T);
    crf_reduce_kernel<<<1, 512>>>((float*)d_out, B);
}

// round 5
// speedup vs baseline: 1.7035x; 1.7035x over previous
#include <cuda_runtime.h>
#include <cstdint>

// CRF loss: mean_b( logZ_b - gold_b )
// Forward recurrence in LINEAR space, one warp per batch, lane = state.
//   e_t[n] = (expM @ e_{t-1})[n] * exp(emit_t[n]) * 2^{-k_t},   off += k_t
// k_t derived from e_{t-1}[0]'s float exponent, read from smem DURING the
// gather and folded into the emission factor -> renorm is off the critical path.
// Dot product: e broadcast via per-warp smem buffer (8x LDS.128), packed
// f32x2 FMAs (16 FFMA2, 4 accumulator chains). Gold score folded in.

#define KSTATES   32
#define START_IDX 30
#define STOP_IDX  31
#define FULLMASK  0xffffffffu
#define LN2       0.6931471805599453f

__device__ float g_scratch[4096];

// s[lane] = sum_p expM[lane][p] * e[p], returned as packed f32x2 partial
// (lo+hi of the return value = full sum). e gathered from shared memory.
__device__ __forceinline__ unsigned long long crf_dot_packed(
    const unsigned long long* __restrict__ Mp, unsigned eaddr)
{
    unsigned long long ev[16];
#pragma unroll
    for (int q = 0; q < 8; q++) {
        asm volatile("ld.shared.v2.u64 {%0,%1}, [%2];"
                     : "=l"(ev[2 * q]), "=l"(ev[2 * q + 1])
                     : "r"(eaddr + 16u * q));
    }
    unsigned long long a0 = 0ull, a1 = 0ull, a2 = 0ull, a3 = 0ull;
#pragma unroll
    for (int i = 0; i < 16; i += 4) {
        asm("fma.rn.f32x2 %0, %1, %2, %0;" : "+l"(a0) : "l"(Mp[i    ]), "l"(ev[i    ]));
        asm("fma.rn.f32x2 %0, %1, %2, %0;" : "+l"(a1) : "l"(Mp[i + 1]), "l"(ev[i + 1]));
        asm("fma.rn.f32x2 %0, %1, %2, %0;" : "+l"(a2) : "l"(Mp[i + 2]), "l"(ev[i + 2]));
        asm("fma.rn.f32x2 %0, %1, %2, %0;" : "+l"(a3) : "l"(Mp[i + 3]), "l"(ev[i + 3]));
    }
    unsigned long long s01, s23, s;
    asm("add.rn.f32x2 %0, %1, %2;" : "=l"(s01) : "l"(a0),  "l"(a1));
    asm("add.rn.f32x2 %0, %1, %2;" : "=l"(s23) : "l"(a2),  "l"(a3));
    asm("add.rn.f32x2 %0, %1, %2;" : "=l"(s)   : "l"(s01), "l"(s23));
    return s;
}

// One recurrence step. Reads e_{t-1} from smem, returns e_t (caller stores it).
// The 2^{-k} renormalizer (from e_{t-1}[0]'s exponent) is folded into expE:
// exact, and entirely parallel to the dot's latency.
__device__ __forceinline__ float crf_step(const unsigned long long* __restrict__ Mp,
                                          unsigned eaddr, float emit, int& off)
{
    float c;
    asm volatile("ld.shared.f32 %0, [%1];" : "=f"(c) : "r"(eaddr));
    int ie = (int)((__float_as_uint(c) >> 23) & 0xFF);
    if (ie == 0) ie = 127;                       // guard c==0/denormal -> r=1
    off += ie - 127;
    float r = __uint_as_float((unsigned)(254 - ie) << 23);   // 2^-(ie-127)
    float expE = __expf(emit) * r;
    unsigned long long eE2;
    asm("mov.b64 %0, {%1, %1};" : "=l"(eE2) : "f"(expE));

    unsigned long long s = crf_dot_packed(Mp, eaddr);
    unsigned long long p;
    asm("mul.rn.f32x2 %0, %1, %2;" : "=l"(p) : "l"(s), "l"(eE2));
    float lo, hi;
    asm("mov.b64 {%0, %1}, %2;" : "=f"(lo), "=f"(hi) : "l"(p));
    return lo + hi;
}

__global__ void __launch_bounds__(128)
crf_forward_kernel(const float* __restrict__ feats,
                   const float* __restrict__ trans,
                   const int*   __restrict__ tags,
                   const int*   __restrict__ lens,
                   int B, int T)
{
    __shared__ __align__(16) float sh_e[4][KSTATES];     // per-warp e buffer
    __shared__ float sh_trans[KSTATES * KSTATES];        // raw transitions (gold)

    const int tid  = threadIdx.x;
    const int wid  = tid >> 5;
    const int lane = tid & 31;

    for (int i = tid; i < KSTATES * KSTATES; i += 128)
        sh_trans[i] = trans[i];
    __syncthreads();

    const int b = blockIdx.x * 4 + wid;
    if (b >= B) return;

    const unsigned eaddr = (unsigned)__cvta_generic_to_shared(&sh_e[wid][0]);

    // Packed expM row for this lane: Mp[q] = (expM[lane][2q], expM[lane][2q+1]).
    // exp(-10000) -> exactly 0, so constraint rows/cols are free.
    unsigned long long Mp[16];
#pragma unroll
    for (int q = 0; q < 16; q++) {
        float m0 = __expf(sh_trans[lane * KSTATES + 2 * q]);
        float m1 = __expf(sh_trans[lane * KSTATES + 2 * q + 1]);
        asm("mov.b64 %0, {%1, %2};" : "=l"(Mp[q]) : "f"(m0), "f"(m1));
    }

    const int len = lens[b];
    const float* fb = feats + (size_t)b * T * KSTATES + lane;
    const int*   tb = tags  + (size_t)b * T;

    sh_e[wid][lane] = (lane == START_IDX) ? 1.0f : 0.0f;
    __syncwarp();

    int   off    = 0;
    float g_emit = 0.0f, g_tr = 0.0f;
    int   tprev  = START_IDX;
    float e;

    // 8-deep prefetch (>= ~640 cyc of cover at ~80 cyc/step > 577 DRAM lat).
    float fbuf[8]; int tbuf[8];
#pragma unroll
    for (int i = 0; i < 8; i++) {
        bool v  = (i < len);
        fbuf[i] = v ? fb[(size_t)i * KSTATES] : 0.0f;
        tbuf[i] = v ? tb[i] : 0;
    }

    const int len8 = len & ~7;
    for (int t0 = 0; t0 < len8; t0 += 8) {
        float fn[8]; int tn[8];
#pragma unroll
        for (int i = 0; i < 8; i++) {
            int  tt = t0 + 8 + i;
            bool v  = (tt < len);
            fn[i] = v ? fb[(size_t)tt * KSTATES] : 0.0f;
            tn[i] = v ? tb[tt] : 0;
        }
#pragma unroll
        for (int j = 0; j < 8; j++) {                 // branch-free body
            e = crf_step(Mp, eaddr, fbuf[j], off);
            sh_e[wid][lane] = e;
            __syncwarp();
            // gold score (independent of the chain; issues in latency shadow)
            int tg = tbuf[j];
            g_emit += (lane == tg) ? fbuf[j] : 0.0f;
            g_tr   += sh_trans[tg * KSTATES + tprev];
            tprev = tg;
            fbuf[j] = fn[j];
            tbuf[j] = tn[j];
        }
    }
    for (int t = len8; t < len; t++) {                // <=7 step tail
        int i = t - len8;
        e = crf_step(Mp, eaddr, fbuf[i], off);
        sh_e[wid][lane] = e;
        __syncwarp();
        int tg = tbuf[i];
        g_emit += (lane == tg) ? fbuf[i] : 0.0f;
        g_tr   += sh_trans[tg * KSTATES + tprev];
        tprev = tg;
    }

    g_tr += sh_trans[STOP_IDX * KSTATES + tprev];

    // forward_score = off*ln2 + log( (expM @ e_final)[STOP] )  (with pending renorm)
    {
        float c;
        asm volatile("ld.shared.f32 %0, [%1];" : "=f"(c) : "r"(eaddr));
        int ie = (int)((__float_as_uint(c) >> 23) & 0xFF);
        if (ie == 0) ie = 127;
        off += ie - 127;
        float r = __uint_as_float((unsigned)(254 - ie) << 23);

        unsigned long long s = crf_dot_packed(Mp, eaddr);
        float lo, hi;
        asm("mov.b64 {%0, %1}, %2;" : "=f"(lo), "=f"(hi) : "l"(s));
        float sfin  = (lo + hi) * r;
        float sstop = __shfl_sync(FULLMASK, sfin, STOP_IDX);
        float fwd   = (float)off * LN2 + __logf(sstop);

#pragma unroll
        for (int d = 16; d; d >>= 1)
            g_emit += __shfl_xor_sync(FULLMASK, g_emit, d);

        if (lane == 0)
            g_scratch[b] = fwd - g_tr - g_emit;
    }
}

__global__ void crf_reduce_kernel(float* __restrict__ out, int B)
{
    __shared__ float sh[512];
    int tid = threadIdx.x;
    float v = 0.0f;
    for (int i = tid; i < B; i += 512)
        v += g_scratch[i];
    sh[tid] = v;
    __syncthreads();
#pragma unroll
    for (int sft = 256; sft > 0; sft >>= 1) {
        if (tid < sft) sh[tid] += sh[tid + sft];
        __syncthreads();
    }
    if (tid == 0) out[0] = sh[0] / (float)B;
}

extern "C" void kernel_launch(void* const* d_in, const int* in_sizes, int n_in,
                              void* d_out, int out_size)
{
    const float* feats = (const float*)d_in[0];   // [B,T,K] f32
    const float* trans = (const float*)d_in[1];   // [K,K]   f32
    const int*   tags  = (const int*)  d_in[2];   // [B,T]   i32
    const int*   lens  = (const int*)  d_in[3];   // [B]     i32

    int B = in_sizes[3];
    int T = in_sizes[2] / B;

    int blocks = (B + 3) / 4;   // 4 warps/block -> 1 warp per SMSP
    crf_forward_kernel<<<blocks, 128>>>(feats, trans, tags, lens, B, T);
    crf_reduce_kernel<<<1, 512>>>((float*)d_out, B);
}